// round 12
// baseline (speedup 1.0000x reference)
#include <cuda_runtime.h>
#include <math.h>

#define BATCH 512
#define TT 5
#define NPROB (BATCH*TT)

// ---------------- scratch (device globals: no allocation allowed) ----------------
__device__ float g_h1[BATCH*10*20*20];   // conv1+pool output
__device__ float g_h2[BATCH*320];        // conv2+pool output (flattened)
__device__ float g_pr[BATCH*20];
__device__ float g_v[BATCH*40];
__device__ __align__(16) float g_wT[118000];  // transposed weights

// ---------------- conv1: (B,1,50,50) -> conv 11x11 -> pool2 -> relu -> (B,10,20,20) ----
__global__ void conv1_kernel(const float* __restrict__ img,
                             const float* __restrict__ w,
                             const float* __restrict__ bias)
{
    __shared__ float sIm[2500];
    __shared__ float sW[1210];
    __shared__ float sB[10];
    int b = blockIdx.x;
    int tid = threadIdx.x;  // 0..399
    for (int i = tid; i < 2500; i += 400) sIm[i] = img[b*2500 + i];
    for (int i = tid; i < 1210; i += 400) sW[i] = w[i];
    if (tid < 10) sB[tid] = bias[tid];
    __syncthreads();

    int oy = tid / 20, ox = tid % 20;
    float acc[10][4];
#pragma unroll
    for (int c = 0; c < 10; c++) { acc[c][0]=0.f; acc[c][1]=0.f; acc[c][2]=0.f; acc[c][3]=0.f; }
    int iy0 = 2*oy, ix0 = 2*ox;
    for (int ky = 0; ky < 11; ky++) {
        const float* row0 = &sIm[(iy0+ky)*50 + ix0];
        const float* row1 = row0 + 50;
#pragma unroll
        for (int kx = 0; kx < 11; kx++) {
            float p00 = row0[kx], p01 = row0[kx+1];
            float p10 = row1[kx], p11 = row1[kx+1];
#pragma unroll
            for (int c = 0; c < 10; c++) {
                float wv = sW[c*121 + ky*11 + kx];
                acc[c][0] += wv*p00; acc[c][1] += wv*p01;
                acc[c][2] += wv*p10; acc[c][3] += wv*p11;
            }
        }
    }
#pragma unroll
    for (int c = 0; c < 10; c++) {
        float m = fmaxf(fmaxf(acc[c][0],acc[c][1]), fmaxf(acc[c][2],acc[c][3]));
        m += sB[c];
        g_h1[((b*10 + c)*20 + oy)*20 + ox] = fmaxf(m, 0.0f);
    }
}

// ---------------- conv2: (B,10,20,20) -> conv 5x5 (20 out) -> pool4 -> relu -> (B,320) ----
__global__ void conv2_kernel(const float* __restrict__ w,   // (20,10,5,5)
                             const float* __restrict__ bias)
{
    __shared__ __align__(16) float sm[9024];
    float* sIn = sm;          // 4000
    float* sW  = sm + 4000;   // 5000 rearranged: [ci][ky][kx][c]
    int b = blockIdx.x;
    int tid = threadIdx.x;    // 0..319
    for (int i = tid; i < 4000; i += 320) sIn[i] = g_h1[b*4000 + i];
    for (int i = tid; i < 5000; i += 320) {
        int c = i % 20;
        int r = i / 20;
        sW[i] = w[c*250 + r];
    }
    __syncthreads();

    bool active = tid < 256;
    int ix = tid & 3, iy = (tid>>2)&3, px = (tid>>4)&3, py = (tid>>6)&3;
    int Y = py*4 + iy, X = px*4 + ix;
    float acc[20];
#pragma unroll
    for (int c = 0; c < 20; c++) acc[c] = 0.0f;
    if (active) {
        for (int ci = 0; ci < 10; ci++) {
            const float* inp = &sIn[ci*400 + Y*20 + X];
#pragma unroll
            for (int ky = 0; ky < 5; ky++) {
#pragma unroll
                for (int kx = 0; kx < 5; kx++) {
                    float pix = inp[ky*20 + kx];
                    const float4* wp = (const float4*)&sW[(ci*25 + ky*5 + kx)*20];
#pragma unroll
                    for (int j = 0; j < 5; j++) {
                        float4 wv = wp[j];
                        acc[4*j+0] += wv.x*pix;
                        acc[4*j+1] += wv.y*pix;
                        acc[4*j+2] += wv.z*pix;
                        acc[4*j+3] += wv.w*pix;
                    }
                }
            }
        }
    }
    __syncthreads();
    float* sConv = sm;
    if (active) {
        int q = py*4 + px;
        int pos = iy*4 + ix;
#pragma unroll
        for (int c = 0; c < 20; c++) sConv[(c*16 + q)*16 + pos] = acc[c];
    }
    __syncthreads();
    {
        int c = tid / 16, qq = tid % 16;
        const float* p = &sConv[(c*16+qq)*16];
        float m = p[0];
#pragma unroll
        for (int k = 1; k < 16; k++) m = fmaxf(m, p[k]);
        m += bias[c];
        g_h2[b*320 + c*16 + qq] = fmaxf(m, 0.0f);
    }
}

// ---------------- weight transpose ----------------
__global__ void transpose_w(const float* __restrict__ w3, const float* __restrict__ w4,
                            const float* __restrict__ pw1, const float* __restrict__ vw1,
                            const float* __restrict__ pw2, const float* __restrict__ vw2,
                            const float* __restrict__ pw3, const float* __restrict__ vw3)
{
    int i = blockIdx.x*blockDim.x + threadIdx.x;
    if (i >= 118000) return;
    float v;
    if (i < 48000)       { int n=i%150, k=i/150;                 v = w3[n*320+k]; }
    else if (i < 63000)  { int j=i-48000;  int n=j%100, k=j/100; v = w4[n*150+k]; }
    else if (i < 77500)  { int j=i-63000;  int n=j%100, k=j/100; v = pw1[n*145+k]; }
    else if (i < 92000)  { int j=i-77500;  int n=j%100, k=j/100; v = vw1[n*145+k]; }
    else if (i < 102000) { int j=i-92000;  int n=j%100, k=j/100; v = pw2[n*100+k]; }
    else if (i < 112000) { int j=i-102000; int n=j%100, k=j/100; v = vw2[n*100+k]; }
    else if (i < 114000) { int j=i-112000; int n=j%20,  k=j/20;  v = pw3[n*100+k]; }
    else                 { int j=i-114000; int n=j%40,  k=j/40;  v = vw3[n*100+k]; }
    g_wT[i] = v;
}

// ---------------- fused MLP: 2 samples per block (256 blocks) --------------
__global__ __launch_bounds__(256) void mlp_kernel(const float* __restrict__ xtraj,
    const float* __restrict__ b3, const float* __restrict__ b4,
    const float* __restrict__ pb1, const float* __restrict__ vb1,
    const float* __restrict__ pb2, const float* __restrict__ vb2,
    const float* __restrict__ pb3, const float* __restrict__ vb3)
{
    __shared__ float sA[2][324];
    __shared__ float sB[2][204];
    int b0 = blockIdx.x*2;
    int tid = threadIdx.x;

    for (int i = tid; i < 640; i += 256) {
        int s = i / 320, k = i % 320;
        sA[s][k] = g_h2[(b0+s)*320 + k];
    }
    __syncthreads();

    if (tid < 150) {
        const float* W = g_wT + tid;
        float a0 = 0.f, a1 = 0.f;
#pragma unroll 8
        for (int k = 0; k < 320; k++) {
            float w = W[k*150];
            a0 = fmaf(sA[0][k], w, a0);
            a1 = fmaf(sA[1][k], w, a1);
        }
        float bb = b3[tid];
        sB[0][tid] = fmaxf(a0+bb, 0.f);
        sB[1][tid] = fmaxf(a1+bb, 0.f);
    }
    __syncthreads();

    float l2a = 0.f, l2b = 0.f;
    if (tid < 100) {
        const float* W = g_wT + 48000 + tid;
        float bb = b4[tid];
#pragma unroll 8
        for (int k = 0; k < 150; k++) {
            float w = W[k*100];
            l2a = fmaf(sB[0][k], w, l2a);
            l2b = fmaf(sB[1][k], w, l2b);
        }
        l2a = fmaxf(l2a+bb, 0.f);
        l2b = fmaxf(l2b+bb, 0.f);
    }
    __syncthreads();
    if (tid < 100) { sA[0][tid] = l2a; sA[1][tid] = l2b; }
    for (int i = tid; i < 90; i += 256) {
        int s = i / 45, j = i % 45;
        sA[s][100+j] = xtraj[(b0+s)*45 + j];
    }
    __syncthreads();

    if (tid < 200) {
        int half = tid >= 100;
        int n = half ? tid - 100 : tid;
        const float* W = g_wT + (half ? 77500 : 63000) + n;
        float bb = (half ? vb1 : pb1)[n];
        float a0 = 0.f, a1 = 0.f;
#pragma unroll 8
        for (int k = 0; k < 145; k++) {
            float w = W[k*100];
            a0 = fmaf(sA[0][k], w, a0);
            a1 = fmaf(sA[1][k], w, a1);
        }
        sB[0][tid] = fmaxf(a0+bb, 0.f);
        sB[1][tid] = fmaxf(a1+bb, 0.f);
    }
    __syncthreads();

    float l4a = 0.f, l4b = 0.f;
    if (tid < 200) {
        int half = tid >= 100;
        int n = half ? tid - 100 : tid;
        int xoff = half ? 100 : 0;
        const float* W = g_wT + (half ? 102000 : 92000) + n;
        float bb = (half ? vb2 : pb2)[n];
#pragma unroll 8
        for (int k = 0; k < 100; k++) {
            float w = W[k*100];
            l4a = fmaf(sB[0][xoff+k], w, l4a);
            l4b = fmaf(sB[1][xoff+k], w, l4b);
        }
        l4a = fmaxf(l4a+bb, 0.f);
        l4b = fmaxf(l4b+bb, 0.f);
    }
    __syncthreads();
    if (tid < 200) { sA[0][tid] = l4a; sA[1][tid] = l4b; }
    __syncthreads();

    if (tid < 20) {
        const float* W = g_wT + 112000 + tid;
        float bb = pb3[tid];
        float a0 = 0.f, a1 = 0.f;
#pragma unroll 8
        for (int k = 0; k < 100; k++) {
            float w = W[k*20];
            a0 = fmaf(sA[0][k], w, a0);
            a1 = fmaf(sA[1][k], w, a1);
        }
        g_pr[(b0+0)*20 + tid] = a0+bb;
        g_pr[(b0+1)*20 + tid] = a1+bb;
    } else if (tid >= 32 && tid < 72) {
        int n = tid - 32;
        const float* W = g_wT + 114000 + n;
        float bb = vb3[n];
        float a0 = 0.f, a1 = 0.f;
#pragma unroll 8
        for (int k = 0; k < 100; k++) {
            float w = W[k*40];
            a0 = fmaf(sA[0][100+k], w, a0);
            a1 = fmaf(sA[1][100+k], w, a1);
        }
        g_v[(b0+0)*40 + n] = a0+bb;
        g_v[(b0+1)*40 + n] = a1+bb;
    }
}

// ---------------- PDHG solver: 2 threads per problem (even/odd lane pair) -------------
// T0 (even lane) owns z[0:12], y[0:9]. T1 (odd lane) owns z[12:24], y[9:17].
// Exchanges via xor-1 shuffles: 8 per half-iteration.
__device__ __forceinline__ float shx(float v)
{
    return __shfl_xor_sync(0xFFFFFFFFu, v, 1);
}

__global__ __launch_bounds__(32) void pdhg_kernel(const float* __restrict__ xtraj,
                                                  const float* __restrict__ x,
                                                  float* __restrict__ out)
{
    int gid = blockIdx.x*32 + threadIdx.x;
    int pi = gid >> 1;          // problem index 0..NPROB-1
    int odd = gid & 1;          // role: 0 = T0, 1 = T1
    int b = pi / TT, t = pi % TT;
    const float* xt = xtraj + b*45;
    const float* xx = x + b*160;

    float r0 = xt[t], r1 = xt[5+t];
    float ddr0 = xt[30+t], ddr1 = xt[35+t], ddr2 = xt[40+t];

    float fc0 = xx[20+t], fc1 = xx[25+t], fc2 = xx[30+t];
    float fc3 = xx[35+t], fc4 = xx[40+t], fc5 = xx[45+t];
    float pe0 = xx[60+t], pe1 = xx[65+t], pe2 = xx[70+t], pe3 = xx[75+t];
    float fe0 = xx[80+t],  fe1 = xx[85+t],  fe2 = xx[90+t],  fe3 = xx[95+t];
    float fe4 = xx[100+t], fe5 = xx[105+t], fe6 = xx[110+t], fe7 = xx[115+t];
    const float* vv = g_v + b*40;
    float v0 = vv[t],    v1 = vv[5+t],  v2 = vv[10+t];
    float v3 = vv[15+t], v4 = vv[20+t], v5 = vv[25+t];
    const float* pp = g_pr + b*20;
    float a24 = -(pp[10+t] - r1), a25 = -(pp[15+t] - r1);
    float a26 = pp[t] - r0,       a27 = pp[5+t] - r0;
    float a28 = -(pe2 - r1), a29 = -(pe3 - r1);
    float a2a = pe0 - r0,    a2b = pe1 - r0;

    // ===== power iteration (split, 25 iters) =====
    float u[12];
#pragma unroll
    for (int i = 0; i < 12; i++) u[i] = 1.0f;

    float w[9];
    for (int it = 0; it < 26; it++) {     // 26th pass computes final w for L
        // exchange 1: T0 sends u[4..11] (=z4..11), T1 sends u[0..3] (=z12..15)
        float snd[8], rcv[8];
        if (!odd) {
#pragma unroll
            for (int i = 0; i < 8; i++) snd[i] = u[4+i];
        } else {
#pragma unroll
            for (int i = 0; i < 8; i++) snd[i] = (i < 4) ? u[i] : 0.0f;
        }
#pragma unroll
        for (int i = 0; i < 8; i++) rcv[i] = shx(snd[i]);

        if (!odd) {
            // rows 0..8; rcv = s12,s13,s14,s15
            w[0] = u[4]+u[5]+u[6]+u[7]+u[8]+u[9];
            w[1] = u[10]+u[11];
            {
                float pq = a26*u[6] + a24*u[4] + a27*u[7] + a25*u[5];
                float qr = a2a*u[10] + a28*u[8] + a2b*u[11] + a29*u[9];
                w[2] = pq + qr;
            }
            w[3] = u[0] - v0*rcv[0] - v2*rcv[2];
            w[4] = u[2] - v1*rcv[0] - v3*rcv[2];
            w[5] = rcv[0] + rcv[2];
            w[6] = u[1] - v2*rcv[1] - v4*rcv[3];
            w[7] = u[3] - v3*rcv[1] - v5*rcv[3];
            w[8] = rcv[1] + rcv[3];
        } else {
            // rows 9..16; rcv = s4..s11
            w[0] = fc0*u[4]  + fc2*u[6]  - rcv[0];
            w[1] = fc1*u[4]  + fc3*u[6]  - rcv[2];
            w[2] = fc2*u[5]  + fc4*u[7]  - rcv[1];
            w[3] = fc3*u[5]  + fc5*u[7]  - rcv[3];
            w[4] = fe0*u[8]  + fe2*u[9]  - rcv[4];
            w[5] = fe1*u[8]  + fe3*u[9]  - rcv[6];
            w[6] = fe4*u[10] + fe6*u[11] - rcv[5];
            w[7] = fe5*u[10] + fe7*u[11] - rcv[7];
            w[8] = 0.0f;
        }
        if (it == 25) break;   // final w computed; exit for L

        // exchange 2: T0 sends w[3..8] (=y3..8), T1 sends w[0..7] (=y9..16)
        if (!odd) {
#pragma unroll
            for (int i = 0; i < 8; i++) snd[i] = (i < 6) ? w[3+i] : 0.0f;
        } else {
#pragma unroll
            for (int i = 0; i < 8; i++) snd[i] = w[i];
        }
#pragma unroll
        for (int i = 0; i < 8; i++) rcv[i] = shx(snd[i]);

        float un[12];
        if (!odd) {
            // coords 0..11; rcv = y9..y16
            un[0] = w[3]; un[1] = w[6]; un[2] = w[4]; un[3] = w[7];
            un[4]  = w[0] + a24*w[2] - rcv[0];
            un[5]  = w[0] + a25*w[2] - rcv[2];
            un[6]  = w[0] + a26*w[2] - rcv[1];
            un[7]  = w[0] + a27*w[2] - rcv[3];
            un[8]  = w[0] + a28*w[2] - rcv[4];
            un[9]  = w[0] + a29*w[2] - rcv[6];
            un[10] = w[1] + a2a*w[2] - rcv[5];
            un[11] = w[1] + a2b*w[2] - rcv[7];
        } else {
            // coords 12..23; rcv = y3..y8 (slots 0..5)
            un[0] = -v0*rcv[0] - v1*rcv[1] + rcv[2];
            un[1] = -v2*rcv[3] - v3*rcv[4] + rcv[5];
            un[2] = -v2*rcv[0] - v3*rcv[1] + rcv[2];
            un[3] = -v4*rcv[3] - v5*rcv[4] + rcv[5];
            un[4]  = fc0*w[0] + fc1*w[1];
            un[5]  = fc2*w[2] + fc3*w[3];
            un[6]  = fc2*w[0] + fc3*w[1];
            un[7]  = fc4*w[2] + fc5*w[3];
            un[8]  = fe0*w[4] + fe1*w[5];
            un[9]  = fe2*w[4] + fe3*w[5];
            un[10] = fe4*w[6] + fe5*w[7];
            un[11] = fe6*w[6] + fe7*w[7];
        }
        float nn = 0.0f;
#pragma unroll
        for (int i = 0; i < 12; i++) nn += un[i]*un[i];
        float tot = nn + shx(nn);
        float inv = 1.0f/(sqrtf(tot) + 1e-12f);
#pragma unroll
        for (int i = 0; i < 12; i++) u[i] = un[i]*inv;
    }
    float ss = 0.0f;
#pragma unroll
    for (int e = 0; e < 9; e++) ss += w[e]*w[e];   // T1: w[8]=0
    float Ltot = ss + shx(ss);
    float L = sqrtf(Ltot);
    float tau = 0.9f/(L + 1e-8f);
    float sig = tau;

    // ===== PDHG main loop (split, 400 iters) =====
    float z[12], zb[12], y[9];
#pragma unroll
    for (int i = 0; i < 12; i++) { z[i] = 0.0f; zb[i] = 0.0f; }
#pragma unroll
    for (int e = 0; e < 9; e++) y[e] = 0.0f;

    for (int it = 0; it < 400; it++) {
        // exchange 1: zb halves
        float snd[8], rcv[8];
        if (!odd) {
#pragma unroll
            for (int i = 0; i < 8; i++) snd[i] = zb[4+i];
        } else {
#pragma unroll
            for (int i = 0; i < 8; i++) snd[i] = (i < 4) ? zb[i] : 0.0f;
        }
#pragma unroll
        for (int i = 0; i < 8; i++) rcv[i] = shx(snd[i]);

        if (!odd) {
            // y0..y8 updates; rcv = zb12..zb15
            y[0] += sig*((zb[4]+zb[5]+zb[6]+zb[7]+zb[8]+zb[9]) - ddr0);
            y[1] += sig*((zb[10]+zb[11]) - ddr1);
            {
                float pq = a26*zb[6] + a24*zb[4] + a27*zb[7] + a25*zb[5];
                float qr = a2a*zb[10] + a28*zb[8] + a2b*zb[11] + a29*zb[9];
                y[2] += sig*((pq + qr) - ddr2);
            }
            y[3] += sig*(zb[0] - v0*rcv[0] - v2*rcv[2]);
            y[4] += sig*(zb[2] - v1*rcv[0] - v3*rcv[2]);
            y[5] += sig*((rcv[0] + rcv[2]) - 1.0f);
            y[6] += sig*(zb[1] - v2*rcv[1] - v4*rcv[3]);
            y[7] += sig*(zb[3] - v3*rcv[1] - v5*rcv[3]);
            y[8] += sig*((rcv[1] + rcv[3]) - 1.0f);
        } else {
            // y9..y16 (local 0..7); rcv = zb4..zb11
            y[0] += sig*(fc0*zb[4]  + fc2*zb[6]  - rcv[0]);
            y[1] += sig*(fc1*zb[4]  + fc3*zb[6]  - rcv[2]);
            y[2] += sig*(fc2*zb[5]  + fc4*zb[7]  - rcv[1]);
            y[3] += sig*(fc3*zb[5]  + fc5*zb[7]  - rcv[3]);
            y[4] += sig*(fe0*zb[8]  + fe2*zb[9]  - rcv[4]);
            y[5] += sig*(fe1*zb[8]  + fe3*zb[9]  - rcv[6]);
            y[6] += sig*(fe4*zb[10] + fe6*zb[11] - rcv[5]);
            y[7] += sig*(fe5*zb[10] + fe7*zb[11] - rcv[7]);
        }

        // exchange 2: y halves
        if (!odd) {
#pragma unroll
            for (int i = 0; i < 8; i++) snd[i] = (i < 6) ? y[3+i] : 0.0f;
        } else {
#pragma unroll
            for (int i = 0; i < 8; i++) snd[i] = y[i];
        }
#pragma unroll
        for (int i = 0; i < 8; i++) rcv[i] = shx(snd[i]);

        if (!odd) {
            // coords 0..11; rcv = y9..y16
            float g0 = y[3], g1 = y[6], g2 = y[4], g3 = y[7];
            float g4  = y[0] + a24*y[2] - rcv[0];
            float g5  = y[0] + a25*y[2] - rcv[2];
            float g6  = y[0] + a26*y[2] - rcv[1];
            float g7  = y[0] + a27*y[2] - rcv[3];
            float g8  = y[0] + a28*y[2] - rcv[4];
            float g9  = y[0] + a29*y[2] - rcv[6];
            float g10 = y[1] + a2a*y[2] - rcv[5];
            float g11 = y[1] + a2b*y[2] - rcv[7];
            // free coords 0..3
            {
                float zn;
                zn = z[0] - tau*g0;  zb[0] = 2.0f*zn - z[0];  z[0] = zn;
                zn = z[1] - tau*g1;  zb[1] = 2.0f*zn - z[1];  z[1] = zn;
                zn = z[2] - tau*g2;  zb[2] = 2.0f*zn - z[2];  z[2] = zn;
                zn = z[3] - tau*g3;  zb[3] = 2.0f*zn - z[3];  z[3] = zn;
            }
            // L1 coords 4..7
            {
                float gg, a, zn;
                gg = z[4] - tau*g4;  a = fabsf(gg) - tau;  zn = (a > 0.f) ? copysignf(a, gg) : 0.f;
                zb[4] = 2.0f*zn - z[4];  z[4] = zn;
                gg = z[5] - tau*g5;  a = fabsf(gg) - tau;  zn = (a > 0.f) ? copysignf(a, gg) : 0.f;
                zb[5] = 2.0f*zn - z[5];  z[5] = zn;
                gg = z[6] - tau*g6;  a = fabsf(gg) - tau;  zn = (a > 0.f) ? copysignf(a, gg) : 0.f;
                zb[6] = 2.0f*zn - z[6];  z[6] = zn;
                gg = z[7] - tau*g7;  a = fabsf(gg) - tau;  zn = (a > 0.f) ? copysignf(a, gg) : 0.f;
                zb[7] = 2.0f*zn - z[7];  z[7] = zn;
            }
            // free coords 8..11
            {
                float zn;
                zn = z[8]  - tau*g8;   zb[8]  = 2.0f*zn - z[8];   z[8]  = zn;
                zn = z[9]  - tau*g9;   zb[9]  = 2.0f*zn - z[9];   z[9]  = zn;
                zn = z[10] - tau*g10;  zb[10] = 2.0f*zn - z[10];  z[10] = zn;
                zn = z[11] - tau*g11;  zb[11] = 2.0f*zn - z[11];  z[11] = zn;
            }
        } else {
            // coords 12..23 (all nonneg); rcv = y3..y8 in slots 0..5
            float g12 = -v0*rcv[0] - v1*rcv[1] + rcv[2];
            float g13 = -v2*rcv[3] - v3*rcv[4] + rcv[5];
            float g14 = -v2*rcv[0] - v3*rcv[1] + rcv[2];
            float g15 = -v4*rcv[3] - v5*rcv[4] + rcv[5];
            float g16 = fc0*y[0] + fc1*y[1];
            float g17 = fc2*y[2] + fc3*y[3];
            float g18 = fc2*y[0] + fc3*y[1];
            float g19 = fc4*y[2] + fc5*y[3];
            float g20 = fe0*y[4] + fe1*y[5];
            float g21 = fe2*y[4] + fe3*y[5];
            float g22 = fe4*y[6] + fe5*y[7];
            float g23 = fe6*y[6] + fe7*y[7];
            float gs[12] = {g12,g13,g14,g15,g16,g17,g18,g19,g20,g21,g22,g23};
#pragma unroll
            for (int k = 0; k < 12; k++) {
                float zn = fmaxf(z[k] - tau*gs[k], 0.0f);
                zb[k] = 2.0f*zn - z[k];
                z[k] = zn;
            }
        }
    }

    // ===== outputs =====
    if (!odd) {
        // p, f (scaled by 100)
#pragma unroll
        for (int i = 0; i < 4; i++) out[b*100 + i*5 + t]      = 100.0f * z[i];
#pragma unroll
        for (int i = 0; i < 4; i++) out[b*100 + 20 + i*5 + t] = 100.0f * z[4+i];
    } else {
        // tail: 12 of the 60 tail outputs of sample b
#pragma unroll
        for (int j = 0; j < 12; j++) {
            int jj = t*12 + j;
            if (jj < 20) out[b*100 + 40 + jj] = 1000.0f*(g_pr[b*20 + jj] - xx[jj]);
            else {
                int k = jj - 20;
                out[b*100 + 60 + k] = 1000.0f*(g_v[b*40 + k] - xx[120 + k]);
            }
        }
    }
}

// ---------------- launch ----------------
extern "C" void kernel_launch(void* const* d_in, const int* in_sizes, int n_in,
                              void* d_out, int out_size)
{
    const float* xtraj = (const float*)d_in[0];
    const float* x     = (const float*)d_in[1];
    const float* x_img = (const float*)d_in[2];
    const float* cw1   = (const float*)d_in[3];
    const float* cb1   = (const float*)d_in[4];
    const float* cw2   = (const float*)d_in[5];
    const float* cb2   = (const float*)d_in[6];
    const float* w3    = (const float*)d_in[7];
    const float* b3    = (const float*)d_in[8];
    const float* w4    = (const float*)d_in[9];
    const float* b4    = (const float*)d_in[10];
    const float* pw1   = (const float*)d_in[11];
    const float* pb1   = (const float*)d_in[12];
    const float* pw2   = (const float*)d_in[13];
    const float* pb2   = (const float*)d_in[14];
    const float* pw3   = (const float*)d_in[15];
    const float* pb3   = (const float*)d_in[16];
    const float* vw1   = (const float*)d_in[17];
    const float* vb1   = (const float*)d_in[18];
    const float* vw2   = (const float*)d_in[19];
    const float* vb2   = (const float*)d_in[20];
    const float* vw3   = (const float*)d_in[21];
    const float* vb3   = (const float*)d_in[22];
    float* out = (float*)d_out;

    transpose_w<<<(118000 + 255)/256, 256>>>(w3, w4, pw1, vw1, pw2, vw2, pw3, vw3);
    conv1_kernel<<<BATCH, 400>>>(x_img, cw1, cb1);
    conv2_kernel<<<BATCH, 320>>>(cw2, cb2);
    mlp_kernel<<<BATCH/2, 256>>>(xtraj, b3, b4, pb1, vb1, pb2, vb2, pb3, vb3);
    pdhg_kernel<<<(NPROB*2)/32, 32>>>(xtraj, x, out);
}

// round 13
// speedup vs baseline: 1.0378x; 1.0378x over previous
#include <cuda_runtime.h>
#include <math.h>

#define BATCH 512
#define TT 5
#define NPROB (BATCH*TT)

// ---------------- scratch (device globals: no allocation allowed) ----------------
__device__ float g_h1[BATCH*10*20*20];   // conv1+pool output
__device__ float g_h2[BATCH*320];        // conv2+pool output (flattened)
__device__ float g_pr[BATCH*20];
__device__ float g_v[BATCH*40];
__device__ __align__(16) float g_wT[118000];  // transposed weights

// ---------------- conv1: (B,1,50,50) -> conv 11x11 -> pool2 -> relu -> (B,10,20,20) ----
__global__ void conv1_kernel(const float* __restrict__ img,
                             const float* __restrict__ w,
                             const float* __restrict__ bias)
{
    __shared__ float sIm[2500];
    __shared__ float sW[1210];
    __shared__ float sB[10];
    int b = blockIdx.x;
    int tid = threadIdx.x;  // 0..399
    for (int i = tid; i < 2500; i += 400) sIm[i] = img[b*2500 + i];
    for (int i = tid; i < 1210; i += 400) sW[i] = w[i];
    if (tid < 10) sB[tid] = bias[tid];
    __syncthreads();

    int oy = tid / 20, ox = tid % 20;
    float acc[10][4];
#pragma unroll
    for (int c = 0; c < 10; c++) { acc[c][0]=0.f; acc[c][1]=0.f; acc[c][2]=0.f; acc[c][3]=0.f; }
    int iy0 = 2*oy, ix0 = 2*ox;
    for (int ky = 0; ky < 11; ky++) {
        const float* row0 = &sIm[(iy0+ky)*50 + ix0];
        const float* row1 = row0 + 50;
#pragma unroll
        for (int kx = 0; kx < 11; kx++) {
            float p00 = row0[kx], p01 = row0[kx+1];
            float p10 = row1[kx], p11 = row1[kx+1];
#pragma unroll
            for (int c = 0; c < 10; c++) {
                float wv = sW[c*121 + ky*11 + kx];
                acc[c][0] += wv*p00; acc[c][1] += wv*p01;
                acc[c][2] += wv*p10; acc[c][3] += wv*p11;
            }
        }
    }
#pragma unroll
    for (int c = 0; c < 10; c++) {
        float m = fmaxf(fmaxf(acc[c][0],acc[c][1]), fmaxf(acc[c][2],acc[c][3]));
        m += sB[c];
        g_h1[((b*10 + c)*20 + oy)*20 + ox] = fmaxf(m, 0.0f);
    }
}

// ---------------- conv2: (B,10,20,20) -> conv 5x5 (20 out) -> pool4 -> relu -> (B,320) ----
__global__ void conv2_kernel(const float* __restrict__ w,   // (20,10,5,5)
                             const float* __restrict__ bias)
{
    __shared__ __align__(16) float sm[9024];
    float* sIn = sm;          // 4000
    float* sW  = sm + 4000;   // 5000 rearranged: [ci][ky][kx][c]
    int b = blockIdx.x;
    int tid = threadIdx.x;    // 0..319
    for (int i = tid; i < 4000; i += 320) sIn[i] = g_h1[b*4000 + i];
    for (int i = tid; i < 5000; i += 320) {
        int c = i % 20;
        int r = i / 20;
        sW[i] = w[c*250 + r];
    }
    __syncthreads();

    bool active = tid < 256;
    int ix = tid & 3, iy = (tid>>2)&3, px = (tid>>4)&3, py = (tid>>6)&3;
    int Y = py*4 + iy, X = px*4 + ix;
    float acc[20];
#pragma unroll
    for (int c = 0; c < 20; c++) acc[c] = 0.0f;
    if (active) {
        for (int ci = 0; ci < 10; ci++) {
            const float* inp = &sIn[ci*400 + Y*20 + X];
#pragma unroll
            for (int ky = 0; ky < 5; ky++) {
#pragma unroll
                for (int kx = 0; kx < 5; kx++) {
                    float pix = inp[ky*20 + kx];
                    const float4* wp = (const float4*)&sW[(ci*25 + ky*5 + kx)*20];
#pragma unroll
                    for (int j = 0; j < 5; j++) {
                        float4 wv = wp[j];
                        acc[4*j+0] += wv.x*pix;
                        acc[4*j+1] += wv.y*pix;
                        acc[4*j+2] += wv.z*pix;
                        acc[4*j+3] += wv.w*pix;
                    }
                }
            }
        }
    }
    __syncthreads();
    float* sConv = sm;
    if (active) {
        int q = py*4 + px;
        int pos = iy*4 + ix;
#pragma unroll
        for (int c = 0; c < 20; c++) sConv[(c*16 + q)*16 + pos] = acc[c];
    }
    __syncthreads();
    {
        int c = tid / 16, qq = tid % 16;
        const float* p = &sConv[(c*16+qq)*16];
        float m = p[0];
#pragma unroll
        for (int k = 1; k < 16; k++) m = fmaxf(m, p[k]);
        m += bias[c];
        g_h2[b*320 + c*16 + qq] = fmaxf(m, 0.0f);
    }
}

// ---------------- weight transpose ----------------
__global__ void transpose_w(const float* __restrict__ w3, const float* __restrict__ w4,
                            const float* __restrict__ pw1, const float* __restrict__ vw1,
                            const float* __restrict__ pw2, const float* __restrict__ vw2,
                            const float* __restrict__ pw3, const float* __restrict__ vw3)
{
    int i = blockIdx.x*blockDim.x + threadIdx.x;
    if (i >= 118000) return;
    float v;
    if (i < 48000)       { int n=i%150, k=i/150;                 v = w3[n*320+k]; }
    else if (i < 63000)  { int j=i-48000;  int n=j%100, k=j/100; v = w4[n*150+k]; }
    else if (i < 77500)  { int j=i-63000;  int n=j%100, k=j/100; v = pw1[n*145+k]; }
    else if (i < 92000)  { int j=i-77500;  int n=j%100, k=j/100; v = vw1[n*145+k]; }
    else if (i < 102000) { int j=i-92000;  int n=j%100, k=j/100; v = pw2[n*100+k]; }
    else if (i < 112000) { int j=i-102000; int n=j%100, k=j/100; v = vw2[n*100+k]; }
    else if (i < 114000) { int j=i-112000; int n=j%20,  k=j/20;  v = pw3[n*100+k]; }
    else                 { int j=i-114000; int n=j%40,  k=j/40;  v = vw3[n*100+k]; }
    g_wT[i] = v;
}

// ---------------- fused MLP: 2 samples per block (256 blocks) --------------
__global__ __launch_bounds__(256) void mlp_kernel(const float* __restrict__ xtraj,
    const float* __restrict__ b3, const float* __restrict__ b4,
    const float* __restrict__ pb1, const float* __restrict__ vb1,
    const float* __restrict__ pb2, const float* __restrict__ vb2,
    const float* __restrict__ pb3, const float* __restrict__ vb3)
{
    __shared__ float sA[2][324];
    __shared__ float sB[2][204];
    int b0 = blockIdx.x*2;
    int tid = threadIdx.x;

    for (int i = tid; i < 640; i += 256) {
        int s = i / 320, k = i % 320;
        sA[s][k] = g_h2[(b0+s)*320 + k];
    }
    __syncthreads();

    if (tid < 150) {
        const float* W = g_wT + tid;
        float a0 = 0.f, a1 = 0.f;
#pragma unroll 8
        for (int k = 0; k < 320; k++) {
            float w = W[k*150];
            a0 = fmaf(sA[0][k], w, a0);
            a1 = fmaf(sA[1][k], w, a1);
        }
        float bb = b3[tid];
        sB[0][tid] = fmaxf(a0+bb, 0.f);
        sB[1][tid] = fmaxf(a1+bb, 0.f);
    }
    __syncthreads();

    float l2a = 0.f, l2b = 0.f;
    if (tid < 100) {
        const float* W = g_wT + 48000 + tid;
        float bb = b4[tid];
#pragma unroll 8
        for (int k = 0; k < 150; k++) {
            float w = W[k*100];
            l2a = fmaf(sB[0][k], w, l2a);
            l2b = fmaf(sB[1][k], w, l2b);
        }
        l2a = fmaxf(l2a+bb, 0.f);
        l2b = fmaxf(l2b+bb, 0.f);
    }
    __syncthreads();
    if (tid < 100) { sA[0][tid] = l2a; sA[1][tid] = l2b; }
    for (int i = tid; i < 90; i += 256) {
        int s = i / 45, j = i % 45;
        sA[s][100+j] = xtraj[(b0+s)*45 + j];
    }
    __syncthreads();

    if (tid < 200) {
        int half = tid >= 100;
        int n = half ? tid - 100 : tid;
        const float* W = g_wT + (half ? 77500 : 63000) + n;
        float bb = (half ? vb1 : pb1)[n];
        float a0 = 0.f, a1 = 0.f;
#pragma unroll 8
        for (int k = 0; k < 145; k++) {
            float w = W[k*100];
            a0 = fmaf(sA[0][k], w, a0);
            a1 = fmaf(sA[1][k], w, a1);
        }
        sB[0][tid] = fmaxf(a0+bb, 0.f);
        sB[1][tid] = fmaxf(a1+bb, 0.f);
    }
    __syncthreads();

    float l4a = 0.f, l4b = 0.f;
    if (tid < 200) {
        int half = tid >= 100;
        int n = half ? tid - 100 : tid;
        int xoff = half ? 100 : 0;
        const float* W = g_wT + (half ? 102000 : 92000) + n;
        float bb = (half ? vb2 : pb2)[n];
#pragma unroll 8
        for (int k = 0; k < 100; k++) {
            float w = W[k*100];
            l4a = fmaf(sB[0][xoff+k], w, l4a);
            l4b = fmaf(sB[1][xoff+k], w, l4b);
        }
        l4a = fmaxf(l4a+bb, 0.f);
        l4b = fmaxf(l4b+bb, 0.f);
    }
    __syncthreads();
    if (tid < 200) { sA[0][tid] = l4a; sA[1][tid] = l4b; }
    __syncthreads();

    if (tid < 20) {
        const float* W = g_wT + 112000 + tid;
        float bb = pb3[tid];
        float a0 = 0.f, a1 = 0.f;
#pragma unroll 8
        for (int k = 0; k < 100; k++) {
            float w = W[k*20];
            a0 = fmaf(sA[0][k], w, a0);
            a1 = fmaf(sA[1][k], w, a1);
        }
        g_pr[(b0+0)*20 + tid] = a0+bb;
        g_pr[(b0+1)*20 + tid] = a1+bb;
    } else if (tid >= 32 && tid < 72) {
        int n = tid - 32;
        const float* W = g_wT + 114000 + n;
        float bb = vb3[n];
        float a0 = 0.f, a1 = 0.f;
#pragma unroll 8
        for (int k = 0; k < 100; k++) {
            float w = W[k*40];
            a0 = fmaf(sA[0][100+k], w, a0);
            a1 = fmaf(sA[1][100+k], w, a1);
        }
        g_v[(b0+0)*40 + n] = a0+bb;
        g_v[(b0+1)*40 + n] = a1+bb;
    }
}

// ---------------- PDHG solver: 2 WARPS per 32 problems, warp-uniform roles ----------
// Block = 64 threads. Warp 0 = T0 role (z[0:12], y[0:9]) for problems base..base+31.
// Warp 1 = T1 role (z[12:24], y[9:17]) for the same problems (lane <-> lane pairing).
// Exchange via double-buffered smem, 2 __syncthreads per iteration.
__global__ __launch_bounds__(64) void pdhg_kernel(const float* __restrict__ xtraj,
                                                  const float* __restrict__ x,
                                                  float* __restrict__ out)
{
    __shared__ float zbT0[2][32][9];  // T0 -> T1 : zb4..11  (8 used)
    __shared__ float zbT1[2][32][5];  // T1 -> T0 : zb12..15 (4 used)
    __shared__ float yT0 [2][32][7];  // T0 -> T1 : y3..8    (6 used)
    __shared__ float yT1 [2][32][9];  // T1 -> T0 : y9..16   (8 used)
    __shared__ float red [2][32][2];  // norm partials

    int lane = threadIdx.x & 31;
    int odd  = threadIdx.x >> 5;      // warp-uniform role
    int pi = blockIdx.x*32 + lane;
    int b = pi / TT, t = pi % TT;
    const float* xt = xtraj + b*45;
    const float* xx = x + b*160;

    float r0 = xt[t], r1 = xt[5+t];
    float ddr0 = xt[30+t], ddr1 = xt[35+t], ddr2 = xt[40+t];

    float fc0 = xx[20+t], fc1 = xx[25+t], fc2 = xx[30+t];
    float fc3 = xx[35+t], fc4 = xx[40+t], fc5 = xx[45+t];
    float pe0 = xx[60+t], pe1 = xx[65+t], pe2 = xx[70+t], pe3 = xx[75+t];
    float fe0 = xx[80+t],  fe1 = xx[85+t],  fe2 = xx[90+t],  fe3 = xx[95+t];
    float fe4 = xx[100+t], fe5 = xx[105+t], fe6 = xx[110+t], fe7 = xx[115+t];
    const float* vv = g_v + b*40;
    float v0 = vv[t],    v1 = vv[5+t],  v2 = vv[10+t];
    float v3 = vv[15+t], v4 = vv[20+t], v5 = vv[25+t];
    const float* pp = g_pr + b*20;
    float a24 = -(pp[10+t] - r1), a25 = -(pp[15+t] - r1);
    float a26 = pp[t] - r0,       a27 = pp[5+t] - r0;
    float a28 = -(pe2 - r1), a29 = -(pe3 - r1);
    float a2a = pe0 - r0,    a2b = pe1 - r0;

    // ===== power iteration (split, 25 iters + final w pass) =====
    float u[12];
#pragma unroll
    for (int i = 0; i < 12; i++) u[i] = 1.0f;
    float w[9];

    for (int it = 0; it <= 25; it++) {
        int buf = it & 1;
        if (!odd) {
#pragma unroll
            for (int i = 0; i < 8; i++) zbT0[buf][lane][i] = u[4+i];
        } else {
#pragma unroll
            for (int i = 0; i < 4; i++) zbT1[buf][lane][i] = u[i];
        }
        __syncthreads();

        if (!odd) {
            float rc0 = zbT1[buf][lane][0], rc1 = zbT1[buf][lane][1];
            float rc2 = zbT1[buf][lane][2], rc3 = zbT1[buf][lane][3];
            w[0] = u[4]+u[5]+u[6]+u[7]+u[8]+u[9];
            w[1] = u[10]+u[11];
            {
                float pq = a26*u[6] + a24*u[4] + a27*u[7] + a25*u[5];
                float qr = a2a*u[10] + a28*u[8] + a2b*u[11] + a29*u[9];
                w[2] = pq + qr;
            }
            w[3] = u[0] - v0*rc0 - v2*rc2;
            w[4] = u[2] - v1*rc0 - v3*rc2;
            w[5] = rc0 + rc2;
            w[6] = u[1] - v2*rc1 - v4*rc3;
            w[7] = u[3] - v3*rc1 - v5*rc3;
            w[8] = rc1 + rc3;
        } else {
            float rc[8];
#pragma unroll
            for (int i = 0; i < 8; i++) rc[i] = zbT0[buf][lane][i];
            w[0] = fc0*u[4]  + fc2*u[6]  - rc[0];
            w[1] = fc1*u[4]  + fc3*u[6]  - rc[2];
            w[2] = fc2*u[5]  + fc4*u[7]  - rc[1];
            w[3] = fc3*u[5]  + fc5*u[7]  - rc[3];
            w[4] = fe0*u[8]  + fe2*u[9]  - rc[4];
            w[5] = fe1*u[8]  + fe3*u[9]  - rc[6];
            w[6] = fe4*u[10] + fe6*u[11] - rc[5];
            w[7] = fe5*u[10] + fe7*u[11] - rc[7];
            w[8] = 0.0f;
        }
        if (it == 25) break;

        if (!odd) {
#pragma unroll
            for (int i = 0; i < 6; i++) yT0[buf][lane][i] = w[3+i];
        } else {
#pragma unroll
            for (int i = 0; i < 8; i++) yT1[buf][lane][i] = w[i];
        }
        __syncthreads();

        float un[12];
        if (!odd) {
            float rc[8];
#pragma unroll
            for (int i = 0; i < 8; i++) rc[i] = yT1[buf][lane][i];
            un[0] = w[3]; un[1] = w[6]; un[2] = w[4]; un[3] = w[7];
            un[4]  = w[0] + a24*w[2] - rc[0];
            un[5]  = w[0] + a25*w[2] - rc[2];
            un[6]  = w[0] + a26*w[2] - rc[1];
            un[7]  = w[0] + a27*w[2] - rc[3];
            un[8]  = w[0] + a28*w[2] - rc[4];
            un[9]  = w[0] + a29*w[2] - rc[6];
            un[10] = w[1] + a2a*w[2] - rc[5];
            un[11] = w[1] + a2b*w[2] - rc[7];
        } else {
            float rc[6];
#pragma unroll
            for (int i = 0; i < 6; i++) rc[i] = yT0[buf][lane][i];
            un[0] = -v0*rc[0] - v1*rc[1] + rc[2];
            un[1] = -v2*rc[3] - v3*rc[4] + rc[5];
            un[2] = -v2*rc[0] - v3*rc[1] + rc[2];
            un[3] = -v4*rc[3] - v5*rc[4] + rc[5];
            un[4]  = fc0*w[0] + fc1*w[1];
            un[5]  = fc2*w[2] + fc3*w[3];
            un[6]  = fc2*w[0] + fc3*w[1];
            un[7]  = fc4*w[2] + fc5*w[3];
            un[8]  = fe0*w[4] + fe1*w[5];
            un[9]  = fe2*w[4] + fe3*w[5];
            un[10] = fe4*w[6] + fe5*w[7];
            un[11] = fe6*w[6] + fe7*w[7];
        }
        float nn = 0.0f;
#pragma unroll
        for (int i = 0; i < 12; i++) nn += un[i]*un[i];
        red[buf][lane][odd] = nn;
        __syncthreads();
        float tot = nn + red[buf][lane][1-odd];
        float inv = 1.0f/(sqrtf(tot) + 1e-12f);
#pragma unroll
        for (int i = 0; i < 12; i++) u[i] = un[i]*inv;
    }
    float ss = 0.0f;
#pragma unroll
    for (int e = 0; e < 9; e++) ss += w[e]*w[e];
    red[0][lane][odd] = ss;
    __syncthreads();
    float Ltot = ss + red[0][lane][1-odd];
    float L = sqrtf(Ltot);
    float tau = 0.9f/(L + 1e-8f);
    float sig = tau;

    // ===== PDHG main loop (split, 400 iters) =====
    float z[12], zb[12], y[9];
#pragma unroll
    for (int i = 0; i < 12; i++) { z[i] = 0.0f; zb[i] = 0.0f; }
#pragma unroll
    for (int e = 0; e < 9; e++) y[e] = 0.0f;

    for (int it = 0; it < 400; it++) {
        int buf = it & 1;
        // --- exchange zb halves ---
        if (!odd) {
#pragma unroll
            for (int i = 0; i < 8; i++) zbT0[buf][lane][i] = zb[4+i];
        } else {
#pragma unroll
            for (int i = 0; i < 4; i++) zbT1[buf][lane][i] = zb[i];
        }
        __syncthreads();

        if (!odd) {
            float rc0 = zbT1[buf][lane][0], rc1 = zbT1[buf][lane][1];
            float rc2 = zbT1[buf][lane][2], rc3 = zbT1[buf][lane][3];
            y[0] += sig*((zb[4]+zb[5]+zb[6]+zb[7]+zb[8]+zb[9]) - ddr0);
            y[1] += sig*((zb[10]+zb[11]) - ddr1);
            {
                float pq = a26*zb[6] + a24*zb[4] + a27*zb[7] + a25*zb[5];
                float qr = a2a*zb[10] + a28*zb[8] + a2b*zb[11] + a29*zb[9];
                y[2] += sig*((pq + qr) - ddr2);
            }
            y[3] += sig*(zb[0] - v0*rc0 - v2*rc2);
            y[4] += sig*(zb[2] - v1*rc0 - v3*rc2);
            y[5] += sig*((rc0 + rc2) - 1.0f);
            y[6] += sig*(zb[1] - v2*rc1 - v4*rc3);
            y[7] += sig*(zb[3] - v3*rc1 - v5*rc3);
            y[8] += sig*((rc1 + rc3) - 1.0f);
            // share y3..8
#pragma unroll
            for (int i = 0; i < 6; i++) yT0[buf][lane][i] = y[3+i];
        } else {
            float rc[8];
#pragma unroll
            for (int i = 0; i < 8; i++) rc[i] = zbT0[buf][lane][i];
            y[0] += sig*(fc0*zb[4]  + fc2*zb[6]  - rc[0]);
            y[1] += sig*(fc1*zb[4]  + fc3*zb[6]  - rc[2]);
            y[2] += sig*(fc2*zb[5]  + fc4*zb[7]  - rc[1]);
            y[3] += sig*(fc3*zb[5]  + fc5*zb[7]  - rc[3]);
            y[4] += sig*(fe0*zb[8]  + fe2*zb[9]  - rc[4]);
            y[5] += sig*(fe1*zb[8]  + fe3*zb[9]  - rc[6]);
            y[6] += sig*(fe4*zb[10] + fe6*zb[11] - rc[5]);
            y[7] += sig*(fe5*zb[10] + fe7*zb[11] - rc[7]);
#pragma unroll
            for (int i = 0; i < 8; i++) yT1[buf][lane][i] = y[i];
        }
        __syncthreads();

        if (!odd) {
            float rc[8];
#pragma unroll
            for (int i = 0; i < 8; i++) rc[i] = yT1[buf][lane][i];
            float g0 = y[3], g1 = y[6], g2 = y[4], g3 = y[7];
            float g4  = y[0] + a24*y[2] - rc[0];
            float g5  = y[0] + a25*y[2] - rc[2];
            float g6  = y[0] + a26*y[2] - rc[1];
            float g7  = y[0] + a27*y[2] - rc[3];
            float g8  = y[0] + a28*y[2] - rc[4];
            float g9  = y[0] + a29*y[2] - rc[6];
            float g10 = y[1] + a2a*y[2] - rc[5];
            float g11 = y[1] + a2b*y[2] - rc[7];
            float zn;
            zn = z[0] - tau*g0;  zb[0] = 2.0f*zn - z[0];  z[0] = zn;
            zn = z[1] - tau*g1;  zb[1] = 2.0f*zn - z[1];  z[1] = zn;
            zn = z[2] - tau*g2;  zb[2] = 2.0f*zn - z[2];  z[2] = zn;
            zn = z[3] - tau*g3;  zb[3] = 2.0f*zn - z[3];  z[3] = zn;
            float gg, a;
            gg = z[4] - tau*g4;  a = fabsf(gg) - tau;  zn = (a > 0.f) ? copysignf(a, gg) : 0.f;
            zb[4] = 2.0f*zn - z[4];  z[4] = zn;
            gg = z[5] - tau*g5;  a = fabsf(gg) - tau;  zn = (a > 0.f) ? copysignf(a, gg) : 0.f;
            zb[5] = 2.0f*zn - z[5];  z[5] = zn;
            gg = z[6] - tau*g6;  a = fabsf(gg) - tau;  zn = (a > 0.f) ? copysignf(a, gg) : 0.f;
            zb[6] = 2.0f*zn - z[6];  z[6] = zn;
            gg = z[7] - tau*g7;  a = fabsf(gg) - tau;  zn = (a > 0.f) ? copysignf(a, gg) : 0.f;
            zb[7] = 2.0f*zn - z[7];  z[7] = zn;
            zn = z[8]  - tau*g8;   zb[8]  = 2.0f*zn - z[8];   z[8]  = zn;
            zn = z[9]  - tau*g9;   zb[9]  = 2.0f*zn - z[9];   z[9]  = zn;
            zn = z[10] - tau*g10;  zb[10] = 2.0f*zn - z[10];  z[10] = zn;
            zn = z[11] - tau*g11;  zb[11] = 2.0f*zn - z[11];  z[11] = zn;
        } else {
            float rc[6];
#pragma unroll
            for (int i = 0; i < 6; i++) rc[i] = yT0[buf][lane][i];
            float gs[12];
            gs[0] = -v0*rc[0] - v1*rc[1] + rc[2];
            gs[1] = -v2*rc[3] - v3*rc[4] + rc[5];
            gs[2] = -v2*rc[0] - v3*rc[1] + rc[2];
            gs[3] = -v4*rc[3] - v5*rc[4] + rc[5];
            gs[4]  = fc0*y[0] + fc1*y[1];
            gs[5]  = fc2*y[2] + fc3*y[3];
            gs[6]  = fc2*y[0] + fc3*y[1];
            gs[7]  = fc4*y[2] + fc5*y[3];
            gs[8]  = fe0*y[4] + fe1*y[5];
            gs[9]  = fe2*y[4] + fe3*y[5];
            gs[10] = fe4*y[6] + fe5*y[7];
            gs[11] = fe6*y[6] + fe7*y[7];
#pragma unroll
            for (int k = 0; k < 12; k++) {
                float zn = fmaxf(z[k] - tau*gs[k], 0.0f);
                zb[k] = 2.0f*zn - z[k];
                z[k] = zn;
            }
        }
    }

    // ===== outputs =====
    if (!odd) {
#pragma unroll
        for (int i = 0; i < 4; i++) out[b*100 + i*5 + t]      = 100.0f * z[i];
#pragma unroll
        for (int i = 0; i < 4; i++) out[b*100 + 20 + i*5 + t] = 100.0f * z[4+i];
    } else {
#pragma unroll
        for (int j = 0; j < 12; j++) {
            int jj = t*12 + j;
            if (jj < 20) out[b*100 + 40 + jj] = 1000.0f*(g_pr[b*20 + jj] - xx[jj]);
            else {
                int k = jj - 20;
                out[b*100 + 60 + k] = 1000.0f*(g_v[b*40 + k] - xx[120 + k]);
            }
        }
    }
}

// ---------------- launch ----------------
extern "C" void kernel_launch(void* const* d_in, const int* in_sizes, int n_in,
                              void* d_out, int out_size)
{
    const float* xtraj = (const float*)d_in[0];
    const float* x     = (const float*)d_in[1];
    const float* x_img = (const float*)d_in[2];
    const float* cw1   = (const float*)d_in[3];
    const float* cb1   = (const float*)d_in[4];
    const float* cw2   = (const float*)d_in[5];
    const float* cb2   = (const float*)d_in[6];
    const float* w3    = (const float*)d_in[7];
    const float* b3    = (const float*)d_in[8];
    const float* w4    = (const float*)d_in[9];
    const float* b4    = (const float*)d_in[10];
    const float* pw1   = (const float*)d_in[11];
    const float* pb1   = (const float*)d_in[12];
    const float* pw2   = (const float*)d_in[13];
    const float* pb2   = (const float*)d_in[14];
    const float* pw3   = (const float*)d_in[15];
    const float* pb3   = (const float*)d_in[16];
    const float* vw1   = (const float*)d_in[17];
    const float* vb1   = (const float*)d_in[18];
    const float* vw2   = (const float*)d_in[19];
    const float* vb2   = (const float*)d_in[20];
    const float* vw3   = (const float*)d_in[21];
    const float* vb3   = (const float*)d_in[22];
    float* out = (float*)d_out;

    transpose_w<<<(118000 + 255)/256, 256>>>(w3, w4, pw1, vw1, pw2, vw2, pw3, vw3);
    conv1_kernel<<<BATCH, 400>>>(x_img, cw1, cb1);
    conv2_kernel<<<BATCH, 320>>>(cw2, cb2);
    mlp_kernel<<<BATCH/2, 256>>>(xtraj, b3, b4, pb1, vb1, pb2, vb2, pb3, vb3);
    pdhg_kernel<<<NPROB/32, 64>>>(xtraj, x, out);
}

// round 14
// speedup vs baseline: 1.0996x; 1.0595x over previous
#include <cuda_runtime.h>
#include <math.h>

#define BATCH 512
#define TT 5
#define NPROB (BATCH*TT)

// ---------------- scratch (device globals: no allocation allowed) ----------------
__device__ float g_h1[BATCH*10*20*20];   // conv1+pool output
__device__ float g_h2[BATCH*320];        // conv2+pool output (flattened)
__device__ float g_pr[BATCH*20];
__device__ float g_v[BATCH*40];

// ---------------- conv1: (B,1,50,50) -> conv 11x11 -> pool2 -> relu -> (B,10,20,20) ----
__global__ void conv1_kernel(const float* __restrict__ img,
                             const float* __restrict__ w,
                             const float* __restrict__ bias)
{
    __shared__ float sIm[2500];
    __shared__ float sW[1210];
    __shared__ float sB[10];
    int b = blockIdx.x;
    int tid = threadIdx.x;  // 0..399
    for (int i = tid; i < 2500; i += 400) sIm[i] = img[b*2500 + i];
    for (int i = tid; i < 1210; i += 400) sW[i] = w[i];
    if (tid < 10) sB[tid] = bias[tid];
    __syncthreads();

    int oy = tid / 20, ox = tid % 20;
    float acc[10][4];
#pragma unroll
    for (int c = 0; c < 10; c++) { acc[c][0]=0.f; acc[c][1]=0.f; acc[c][2]=0.f; acc[c][3]=0.f; }
    int iy0 = 2*oy, ix0 = 2*ox;
    for (int ky = 0; ky < 11; ky++) {
        const float* row0 = &sIm[(iy0+ky)*50 + ix0];
        const float* row1 = row0 + 50;
#pragma unroll
        for (int kx = 0; kx < 11; kx++) {
            float p00 = row0[kx], p01 = row0[kx+1];
            float p10 = row1[kx], p11 = row1[kx+1];
#pragma unroll
            for (int c = 0; c < 10; c++) {
                float wv = sW[c*121 + ky*11 + kx];
                acc[c][0] += wv*p00; acc[c][1] += wv*p01;
                acc[c][2] += wv*p10; acc[c][3] += wv*p11;
            }
        }
    }
#pragma unroll
    for (int c = 0; c < 10; c++) {
        float m = fmaxf(fmaxf(acc[c][0],acc[c][1]), fmaxf(acc[c][2],acc[c][3]));
        m += sB[c];
        g_h1[((b*10 + c)*20 + oy)*20 + ox] = fmaxf(m, 0.0f);
    }
}

// ---------------- conv2: (B,10,20,20) -> conv 5x5 (20 out) -> pool4 -> relu -> (B,320) ----
__global__ void conv2_kernel(const float* __restrict__ w,   // (20,10,5,5)
                             const float* __restrict__ bias)
{
    __shared__ __align__(16) float sm[9024];
    float* sIn = sm;          // 4000
    float* sW  = sm + 4000;   // 5000 rearranged: [ci][ky][kx][c]
    int b = blockIdx.x;
    int tid = threadIdx.x;    // 0..319
    for (int i = tid; i < 4000; i += 320) sIn[i] = g_h1[b*4000 + i];
    for (int i = tid; i < 5000; i += 320) {
        int c = i % 20;
        int r = i / 20;
        sW[i] = w[c*250 + r];
    }
    __syncthreads();

    bool active = tid < 256;
    int ix = tid & 3, iy = (tid>>2)&3, px = (tid>>4)&3, py = (tid>>6)&3;
    int Y = py*4 + iy, X = px*4 + ix;
    float acc[20];
#pragma unroll
    for (int c = 0; c < 20; c++) acc[c] = 0.0f;
    if (active) {
        for (int ci = 0; ci < 10; ci++) {
            const float* inp = &sIn[ci*400 + Y*20 + X];
#pragma unroll
            for (int ky = 0; ky < 5; ky++) {
#pragma unroll
                for (int kx = 0; kx < 5; kx++) {
                    float pix = inp[ky*20 + kx];
                    const float4* wp = (const float4*)&sW[(ci*25 + ky*5 + kx)*20];
#pragma unroll
                    for (int j = 0; j < 5; j++) {
                        float4 wv = wp[j];
                        acc[4*j+0] += wv.x*pix;
                        acc[4*j+1] += wv.y*pix;
                        acc[4*j+2] += wv.z*pix;
                        acc[4*j+3] += wv.w*pix;
                    }
                }
            }
        }
    }
    __syncthreads();
    float* sConv = sm;
    if (active) {
        int q = py*4 + px;
        int pos = iy*4 + ix;
#pragma unroll
        for (int c = 0; c < 20; c++) sConv[(c*16 + q)*16 + pos] = acc[c];
    }
    __syncthreads();
    {
        int c = tid / 16, qq = tid % 16;
        const float* p = &sConv[(c*16+qq)*16];
        float m = p[0];
#pragma unroll
        for (int k = 1; k < 16; k++) m = fmaxf(m, p[k]);
        m += bias[c];
        g_h2[b*320 + c*16 + qq] = fmaxf(m, 0.0f);
    }
}

// ---------------- fused MLP v3: warp-per-output dot products, original weights -------
// One sample per block (512 blocks), 8 warps. Lanes k-slice each weight row
// (row-major [N][K] -> coalesced), 5-step shfl reduce per output.
__device__ __forceinline__ float wreduce(float p)
{
    p += __shfl_xor_sync(0xFFFFFFFFu, p, 16);
    p += __shfl_xor_sync(0xFFFFFFFFu, p, 8);
    p += __shfl_xor_sync(0xFFFFFFFFu, p, 4);
    p += __shfl_xor_sync(0xFFFFFFFFu, p, 2);
    p += __shfl_xor_sync(0xFFFFFFFFu, p, 1);
    return p;
}

__global__ __launch_bounds__(256) void mlp_kernel(const float* __restrict__ xtraj,
    const float* __restrict__ w3, const float* __restrict__ b3,
    const float* __restrict__ w4, const float* __restrict__ b4,
    const float* __restrict__ pw1, const float* __restrict__ pb1,
    const float* __restrict__ pw2, const float* __restrict__ pb2,
    const float* __restrict__ pw3, const float* __restrict__ pb3,
    const float* __restrict__ vw1, const float* __restrict__ vb1,
    const float* __restrict__ vw2, const float* __restrict__ vb2,
    const float* __restrict__ vw3, const float* __restrict__ vb3)
{
    __shared__ float sX[324];
    __shared__ float sY[204];
    int b = blockIdx.x;
    int tid = threadIdx.x;
    int lane = tid & 31, wid = tid >> 5;   // 8 warps

    // load h2 (320)
    for (int i = tid; i < 320; i += 256) sX[i] = g_h2[b*320 + i];
    __syncthreads();

    // L1: 150 outputs, K=320
    for (int n = wid; n < 150; n += 8) {
        const float* W = w3 + n*320;
        float p = 0.f;
#pragma unroll
        for (int k0 = 0; k0 < 320; k0 += 32) {
            int k = k0 + lane;
            p = fmaf(sX[k], W[k], p);
        }
        p = wreduce(p);
        if (lane == 0) sY[n] = fmaxf(p + b3[n], 0.f);
    }
    __syncthreads();

    // L2: 100 outputs, K=150 (reads sY, writes sX[0:100])
    for (int n = wid; n < 100; n += 8) {
        const float* W = w4 + n*150;
        float p = 0.f;
#pragma unroll
        for (int k0 = 0; k0 < 150; k0 += 32) {
            int k = k0 + lane;
            float xv = (k < 150) ? sY[k] : 0.f;
            float wv = (k < 150) ? W[k] : 0.f;
            p = fmaf(xv, wv, p);
        }
        p = wreduce(p);
        if (lane == 0) sX[n] = fmaxf(p + b4[n], 0.f);
    }
    // concat xtraj into sX[100:145] (independent of L2's sX[0:100] writes)
    for (int i = tid; i < 45; i += 256) sX[100+i] = xtraj[b*45 + i];
    __syncthreads();

    // L3 dual: 200 outputs, K=145 (reads sX[0:145], writes sY[0:200])
    for (int m = wid; m < 200; m += 8) {
        int half = m >= 100;
        int n = half ? m - 100 : m;
        const float* W = (half ? vw1 : pw1) + n*145;
        float p = 0.f;
#pragma unroll
        for (int k0 = 0; k0 < 145; k0 += 32) {
            int k = k0 + lane;
            float xv = (k < 145) ? sX[k] : 0.f;
            float wv = (k < 145) ? W[k] : 0.f;
            p = fmaf(xv, wv, p);
        }
        p = wreduce(p);
        if (lane == 0) sY[m] = fmaxf(p + (half ? vb1 : pb1)[n], 0.f);
    }
    __syncthreads();

    // L4 dual: 200 outputs, K=100 (reads sY, writes sX[0:200])
    for (int m = wid; m < 200; m += 8) {
        int half = m >= 100;
        int n = half ? m - 100 : m;
        const float* X = half ? sY + 100 : sY;
        const float* W = (half ? vw2 : pw2) + n*100;
        float p = 0.f;
#pragma unroll
        for (int k0 = 0; k0 < 100; k0 += 32) {
            int k = k0 + lane;
            float xv = (k < 100) ? X[k] : 0.f;
            float wv = (k < 100) ? W[k] : 0.f;
            p = fmaf(xv, wv, p);
        }
        p = wreduce(p);
        if (lane == 0) sX[m] = fmaxf(p + (half ? vb2 : pb2)[n], 0.f);
    }
    __syncthreads();

    // L5 dual: 60 outputs, K=100, linear, straight to global
    for (int m = wid; m < 60; m += 8) {
        int half = m >= 20;
        int n = half ? m - 20 : m;
        const float* X = half ? sX + 100 : sX;
        const float* W = (half ? vw3 : pw3) + n*100;
        float p = 0.f;
#pragma unroll
        for (int k0 = 0; k0 < 100; k0 += 32) {
            int k = k0 + lane;
            float xv = (k < 100) ? X[k] : 0.f;
            float wv = (k < 100) ? W[k] : 0.f;
            p = fmaf(xv, wv, p);
        }
        p = wreduce(p);
        if (lane == 0) {
            if (half) g_v[b*40 + n]  = p + vb3[n];
            else      g_pr[b*20 + n] = p + pb3[n];
        }
    }
}

// ---------------- PDHG solver (scalar, R11-proven) + fused tail ----------------
struct Co {
    float a24,a25,a26,a27,a28,a29,a2a,a2b;
    float v0,v1,v2,v3,v4,v5;
    float fc0,fc1,fc2,fc3,fc4,fc5;
    float fe0,fe1,fe2,fe3,fe4,fe5,fe6,fe7;
};

__device__ __forceinline__ void amul(const Co& c, const float* s, float* az)
{
    az[0]  = s[4]+s[5]+s[6]+s[7]+s[8]+s[9];
    az[1]  = s[10]+s[11];
    {
        float p = c.a26*s[6] + c.a24*s[4] + c.a27*s[7] + c.a25*s[5];
        float q = c.a2a*s[10] + c.a28*s[8] + c.a2b*s[11] + c.a29*s[9];
        az[2] = p + q;
    }
    az[3]  = s[0] - c.v0*s[12] - c.v2*s[14];
    az[4]  = s[2] - c.v1*s[12] - c.v3*s[14];
    az[5]  = s[12] + s[14];
    az[6]  = s[1] - c.v2*s[13] - c.v4*s[15];
    az[7]  = s[3] - c.v3*s[13] - c.v5*s[15];
    az[8]  = s[13] + s[15];
    az[9]  = c.fc0*s[16] + c.fc2*s[18] - s[4];
    az[10] = c.fc1*s[16] + c.fc3*s[18] - s[6];
    az[11] = c.fc2*s[17] + c.fc4*s[19] - s[5];
    az[12] = c.fc3*s[17] + c.fc5*s[19] - s[7];
    az[13] = c.fe0*s[20] + c.fe2*s[21] - s[8];
    az[14] = c.fe1*s[20] + c.fe3*s[21] - s[10];
    az[15] = c.fe4*s[22] + c.fe6*s[23] - s[9];
    az[16] = c.fe5*s[22] + c.fe7*s[23] - s[11];
}

__device__ __forceinline__ void atmul(const Co& c, const float* y, float* g)
{
    g[0]  = y[3];  g[1] = y[6];  g[2] = y[4];  g[3] = y[7];
    g[4]  = y[0] + c.a24*y[2] - y[9];
    g[5]  = y[0] + c.a25*y[2] - y[11];
    g[6]  = y[0] + c.a26*y[2] - y[10];
    g[7]  = y[0] + c.a27*y[2] - y[12];
    g[8]  = y[0] + c.a28*y[2] - y[13];
    g[9]  = y[0] + c.a29*y[2] - y[15];
    g[10] = y[1] + c.a2a*y[2] - y[14];
    g[11] = y[1] + c.a2b*y[2] - y[16];
    g[12] = -c.v0*y[3] - c.v1*y[4] + y[5];
    g[13] = -c.v2*y[6] - c.v3*y[7] + y[8];
    g[14] = -c.v2*y[3] - c.v3*y[4] + y[5];
    g[15] = -c.v4*y[6] - c.v5*y[7] + y[8];
    g[16] = c.fc0*y[9]  + c.fc1*y[10];
    g[17] = c.fc2*y[11] + c.fc3*y[12];
    g[18] = c.fc2*y[9]  + c.fc3*y[10];
    g[19] = c.fc4*y[11] + c.fc5*y[12];
    g[20] = c.fe0*y[13] + c.fe1*y[14];
    g[21] = c.fe2*y[13] + c.fe3*y[14];
    g[22] = c.fe4*y[15] + c.fe5*y[16];
    g[23] = c.fe6*y[15] + c.fe7*y[16];
}

__global__ __launch_bounds__(32) void pdhg_kernel(const float* __restrict__ xtraj,
                                                  const float* __restrict__ x,
                                                  float* __restrict__ out)
{
    int p = blockIdx.x*blockDim.x + threadIdx.x;
    if (p >= NPROB) return;
    int b = p / TT, t = p % TT;
    const float* xt = xtraj + b*45;
    const float* xx = x + b*160;

    float r0 = xt[t], r1 = xt[5+t];
    float ddr0 = xt[30+t], ddr1 = xt[35+t], ddr2 = xt[40+t];

    Co c;
    c.fc0 = xx[20+t]; c.fc1 = xx[25+t]; c.fc2 = xx[30+t];
    c.fc3 = xx[35+t]; c.fc4 = xx[40+t]; c.fc5 = xx[45+t];
    float pe0 = xx[60+t], pe1 = xx[65+t], pe2 = xx[70+t], pe3 = xx[75+t];
    c.fe0 = xx[80+t];  c.fe1 = xx[85+t];  c.fe2 = xx[90+t];  c.fe3 = xx[95+t];
    c.fe4 = xx[100+t]; c.fe5 = xx[105+t]; c.fe6 = xx[110+t]; c.fe7 = xx[115+t];
    const float* vv = g_v + b*40;
    c.v0 = vv[t];    c.v1 = vv[5+t];  c.v2 = vv[10+t];
    c.v3 = vv[15+t]; c.v4 = vv[20+t]; c.v5 = vv[25+t];
    const float* pp = g_pr + b*20;
    float pr0 = pp[t], pr1 = pp[5+t], pr2 = pp[10+t], pr3 = pp[15+t];
    c.a24 = -(pr2 - r1); c.a25 = -(pr3 - r1); c.a26 = pr0 - r0; c.a27 = pr1 - r0;
    c.a28 = -(pe2 - r1); c.a29 = -(pe3 - r1); c.a2a = pe0 - r0; c.a2b = pe1 - r0;

    // ----- spectral norm: 25 power iterations -----
    float u[24];
#pragma unroll
    for (int i = 0; i < 24; i++) u[i] = 1.0f;
    for (int it = 0; it < 25; it++) {
        float w[17], un[24];
        amul(c, u, w);
        atmul(c, w, un);
        float s = 0.0f;
#pragma unroll
        for (int i = 0; i < 24; i++) s += un[i]*un[i];
        float inv = 1.0f/(sqrtf(s) + 1e-12f);
#pragma unroll
        for (int i = 0; i < 24; i++) u[i] = un[i]*inv;
    }
    float w17[17];
    amul(c, u, w17);
    float s = 0.0f;
#pragma unroll
    for (int e = 0; e < 17; e++) s += w17[e]*w17[e];
    float L = sqrtf(s);
    float tau = 0.9f/(L + 1e-8f);
    float sig = tau;

    // ----- PDHG, 400 iterations -----
    float z[24], zb[24], y[17];
#pragma unroll
    for (int i = 0; i < 24; i++) { z[i] = 0.0f; zb[i] = 0.0f; }
#pragma unroll
    for (int e = 0; e < 17; e++) y[e] = 0.0f;

    for (int it = 0; it < 400; it++) {
        float az[17];
        amul(c, zb, az);
        y[0] += sig*(az[0] - ddr0);
        y[1] += sig*(az[1] - ddr1);
        y[2] += sig*(az[2] - ddr2);
        y[3] += sig*az[3];
        y[4] += sig*az[4];
        y[5] += sig*(az[5] - 1.0f);
        y[6] += sig*az[6];
        y[7] += sig*az[7];
        y[8] += sig*(az[8] - 1.0f);
#pragma unroll
        for (int e = 9; e < 17; e++) y[e] += sig*az[e];

        float g[24];
        atmul(c, y, g);
#pragma unroll
        for (int i = 0; i < 24; i++) g[i] = z[i] - tau*g[i];

        float zn[24];
#pragma unroll
        for (int i = 0; i < 4; i++) zn[i] = g[i];
#pragma unroll
        for (int i = 4; i < 8; i++) {
            float a = fabsf(g[i]) - tau;
            zn[i] = (a > 0.0f) ? copysignf(a, g[i]) : 0.0f;
        }
#pragma unroll
        for (int i = 8; i < 12; i++) zn[i] = g[i];
#pragma unroll
        for (int i = 12; i < 24; i++) zn[i] = fmaxf(g[i], 0.0f);
#pragma unroll
        for (int i = 0; i < 24; i++) {
            zb[i] = 2.0f*zn[i] - z[i];
            z[i] = zn[i];
        }
    }

    // ----- write p, f parts (scaled by 100) -----
#pragma unroll
    for (int i = 0; i < 4; i++) out[b*100 + i*5 + t]      = 100.0f * z[i];
#pragma unroll
    for (int i = 0; i < 4; i++) out[b*100 + 20 + i*5 + t] = 100.0f * z[4+i];

    // ----- fused tail: this thread writes 12 of the 60 tail outputs of sample b -----
#pragma unroll
    for (int j = 0; j < 12; j++) {
        int jj = t*12 + j;
        if (jj < 20) out[b*100 + 40 + jj] = 1000.0f*(g_pr[b*20 + jj] - xx[jj]);
        else {
            int k = jj - 20;
            out[b*100 + 60 + k] = 1000.0f*(g_v[b*40 + k] - xx[120 + k]);
        }
    }
}

// ---------------- launch ----------------
extern "C" void kernel_launch(void* const* d_in, const int* in_sizes, int n_in,
                              void* d_out, int out_size)
{
    const float* xtraj = (const float*)d_in[0];
    const float* x     = (const float*)d_in[1];
    const float* x_img = (const float*)d_in[2];
    const float* cw1   = (const float*)d_in[3];
    const float* cb1   = (const float*)d_in[4];
    const float* cw2   = (const float*)d_in[5];
    const float* cb2   = (const float*)d_in[6];
    const float* w3    = (const float*)d_in[7];
    const float* b3    = (const float*)d_in[8];
    const float* w4    = (const float*)d_in[9];
    const float* b4    = (const float*)d_in[10];
    const float* pw1   = (const float*)d_in[11];
    const float* pb1   = (const float*)d_in[12];
    const float* pw2   = (const float*)d_in[13];
    const float* pb2   = (const float*)d_in[14];
    const float* pw3   = (const float*)d_in[15];
    const float* pb3   = (const float*)d_in[16];
    const float* vw1   = (const float*)d_in[17];
    const float* vb1   = (const float*)d_in[18];
    const float* vw2   = (const float*)d_in[19];
    const float* vb2   = (const float*)d_in[20];
    const float* vw3   = (const float*)d_in[21];
    const float* vb3   = (const float*)d_in[22];
    float* out = (float*)d_out;

    conv1_kernel<<<BATCH, 400>>>(x_img, cw1, cb1);
    conv2_kernel<<<BATCH, 320>>>(cw2, cb2);
    mlp_kernel<<<BATCH, 256>>>(xtraj, w3, b3, w4, b4,
                               pw1, pb1, pw2, pb2, pw3, pb3,
                               vw1, vb1, vw2, vb2, vw3, vb3);
    pdhg_kernel<<<(NPROB + 31)/32, 32>>>(xtraj, x, out);
}

// round 15
// speedup vs baseline: 1.1554x; 1.0508x over previous
#include <cuda_runtime.h>
#include <math.h>

#define BATCH 512
#define TT 5
#define NPROB (BATCH*TT)

// ---------------- scratch (device globals: no allocation allowed) ----------------
__device__ float g_h1[BATCH*10*20*20];   // conv1+pool output
__device__ float g_h2[BATCH*320];        // conv2+pool output (flattened)
__device__ float g_pr[BATCH*20];
__device__ float g_v[BATCH*40];
__device__ __align__(16) float g_wT[118000];  // transposed weights

// ---------------- conv1: (B,1,50,50) -> conv 11x11 -> pool2 -> relu -> (B,10,20,20) ----
__global__ void conv1_kernel(const float* __restrict__ img,
                             const float* __restrict__ w,
                             const float* __restrict__ bias)
{
    __shared__ float sIm[2500];
    __shared__ float sW[1210];
    __shared__ float sB[10];
    int b = blockIdx.x;
    int tid = threadIdx.x;  // 0..399
    for (int i = tid; i < 2500; i += 400) sIm[i] = img[b*2500 + i];
    for (int i = tid; i < 1210; i += 400) sW[i] = w[i];
    if (tid < 10) sB[tid] = bias[tid];
    __syncthreads();

    int oy = tid / 20, ox = tid % 20;
    float acc[10][4];
#pragma unroll
    for (int c = 0; c < 10; c++) { acc[c][0]=0.f; acc[c][1]=0.f; acc[c][2]=0.f; acc[c][3]=0.f; }
    int iy0 = 2*oy, ix0 = 2*ox;
    for (int ky = 0; ky < 11; ky++) {
        const float* row0 = &sIm[(iy0+ky)*50 + ix0];
        const float* row1 = row0 + 50;
#pragma unroll
        for (int kx = 0; kx < 11; kx++) {
            float p00 = row0[kx], p01 = row0[kx+1];
            float p10 = row1[kx], p11 = row1[kx+1];
#pragma unroll
            for (int c = 0; c < 10; c++) {
                float wv = sW[c*121 + ky*11 + kx];
                acc[c][0] += wv*p00; acc[c][1] += wv*p01;
                acc[c][2] += wv*p10; acc[c][3] += wv*p11;
            }
        }
    }
#pragma unroll
    for (int c = 0; c < 10; c++) {
        float m = fmaxf(fmaxf(acc[c][0],acc[c][1]), fmaxf(acc[c][2],acc[c][3]));
        m += sB[c];
        g_h1[((b*10 + c)*20 + oy)*20 + ox] = fmaxf(m, 0.0f);
    }
}

// ---------------- conv2: (B,10,20,20) -> conv 5x5 (20 out) -> pool4 -> relu -> (B,320) ----
__global__ void conv2_kernel(const float* __restrict__ w,   // (20,10,5,5)
                             const float* __restrict__ bias)
{
    __shared__ __align__(16) float sm[9024];
    float* sIn = sm;          // 4000
    float* sW  = sm + 4000;   // 5000 rearranged: [ci][ky][kx][c]
    int b = blockIdx.x;
    int tid = threadIdx.x;    // 0..319
    for (int i = tid; i < 4000; i += 320) sIn[i] = g_h1[b*4000 + i];
    for (int i = tid; i < 5000; i += 320) {
        int c = i % 20;
        int r = i / 20;
        sW[i] = w[c*250 + r];
    }
    __syncthreads();

    bool active = tid < 256;
    int ix = tid & 3, iy = (tid>>2)&3, px = (tid>>4)&3, py = (tid>>6)&3;
    int Y = py*4 + iy, X = px*4 + ix;
    float acc[20];
#pragma unroll
    for (int c = 0; c < 20; c++) acc[c] = 0.0f;
    if (active) {
        for (int ci = 0; ci < 10; ci++) {
            const float* inp = &sIn[ci*400 + Y*20 + X];
#pragma unroll
            for (int ky = 0; ky < 5; ky++) {
#pragma unroll
                for (int kx = 0; kx < 5; kx++) {
                    float pix = inp[ky*20 + kx];
                    const float4* wp = (const float4*)&sW[(ci*25 + ky*5 + kx)*20];
#pragma unroll
                    for (int j = 0; j < 5; j++) {
                        float4 wv = wp[j];
                        acc[4*j+0] += wv.x*pix;
                        acc[4*j+1] += wv.y*pix;
                        acc[4*j+2] += wv.z*pix;
                        acc[4*j+3] += wv.w*pix;
                    }
                }
            }
        }
    }
    __syncthreads();
    float* sConv = sm;
    if (active) {
        int q = py*4 + px;
        int pos = iy*4 + ix;
#pragma unroll
        for (int c = 0; c < 20; c++) sConv[(c*16 + q)*16 + pos] = acc[c];
    }
    __syncthreads();
    {
        int c = tid / 16, qq = tid % 16;
        const float* p = &sConv[(c*16+qq)*16];
        float m = p[0];
#pragma unroll
        for (int k = 1; k < 16; k++) m = fmaxf(m, p[k]);
        m += bias[c];
        g_h2[b*320 + c*16 + qq] = fmaxf(m, 0.0f);
    }
}

// ---------------- weight transpose ----------------
__global__ void transpose_w(const float* __restrict__ w3, const float* __restrict__ w4,
                            const float* __restrict__ pw1, const float* __restrict__ vw1,
                            const float* __restrict__ pw2, const float* __restrict__ vw2,
                            const float* __restrict__ pw3, const float* __restrict__ vw3)
{
    int i = blockIdx.x*blockDim.x + threadIdx.x;
    if (i >= 118000) return;
    float v;
    if (i < 48000)       { int n=i%150, k=i/150;                 v = w3[n*320+k]; }
    else if (i < 63000)  { int j=i-48000;  int n=j%100, k=j/100; v = w4[n*150+k]; }
    else if (i < 77500)  { int j=i-63000;  int n=j%100, k=j/100; v = pw1[n*145+k]; }
    else if (i < 92000)  { int j=i-77500;  int n=j%100, k=j/100; v = vw1[n*145+k]; }
    else if (i < 102000) { int j=i-92000;  int n=j%100, k=j/100; v = pw2[n*100+k]; }
    else if (i < 112000) { int j=i-102000; int n=j%100, k=j/100; v = vw2[n*100+k]; }
    else if (i < 114000) { int j=i-112000; int n=j%20,  k=j/20;  v = pw3[n*100+k]; }
    else                 { int j=i-114000; int n=j%40,  k=j/40;  v = vw3[n*100+k]; }
    g_wT[i] = v;
}

// ---------------- fused MLP: 2 samples/block, split-k dual accumulator chains --------
__global__ __launch_bounds__(256) void mlp_kernel(const float* __restrict__ xtraj,
    const float* __restrict__ b3, const float* __restrict__ b4,
    const float* __restrict__ pb1, const float* __restrict__ vb1,
    const float* __restrict__ pb2, const float* __restrict__ vb2,
    const float* __restrict__ pb3, const float* __restrict__ vb3)
{
    __shared__ float sA[2][324];
    __shared__ float sB[2][204];
    int b0 = blockIdx.x*2;
    int tid = threadIdx.x;

    for (int i = tid; i < 640; i += 256) {
        int s = i / 320, k = i % 320;
        sA[s][k] = g_h2[(b0+s)*320 + k];
    }
    __syncthreads();

    // L1: 320 -> 150 relu (K even)
    if (tid < 150) {
        const float* W = g_wT + tid;
        float a0=0.f, a1=0.f, c0=0.f, c1=0.f;
#pragma unroll 4
        for (int k = 0; k < 320; k += 2) {
            float w0 = W[k*150], w1 = W[(k+1)*150];
            a0 = fmaf(sA[0][k],   w0, a0);
            a1 = fmaf(sA[1][k],   w0, a1);
            c0 = fmaf(sA[0][k+1], w1, c0);
            c1 = fmaf(sA[1][k+1], w1, c1);
        }
        float bb = b3[tid];
        sB[0][tid] = fmaxf(a0+c0+bb, 0.f);
        sB[1][tid] = fmaxf(a1+c1+bb, 0.f);
    }
    __syncthreads();

    // L2: 150 -> 100 relu (K even)
    float l2a = 0.f, l2b = 0.f;
    if (tid < 100) {
        const float* W = g_wT + 48000 + tid;
        float bb = b4[tid];
        float a0=0.f, a1=0.f, c0=0.f, c1=0.f;
#pragma unroll 4
        for (int k = 0; k < 150; k += 2) {
            float w0 = W[k*100], w1 = W[(k+1)*100];
            a0 = fmaf(sB[0][k],   w0, a0);
            a1 = fmaf(sB[1][k],   w0, a1);
            c0 = fmaf(sB[0][k+1], w1, c0);
            c1 = fmaf(sB[1][k+1], w1, c1);
        }
        l2a = fmaxf(a0+c0+bb, 0.f);
        l2b = fmaxf(a1+c1+bb, 0.f);
    }
    __syncthreads();
    if (tid < 100) { sA[0][tid] = l2a; sA[1][tid] = l2b; }
    for (int i = tid; i < 90; i += 256) {
        int s = i / 45, j = i % 45;
        sA[s][100+j] = xtraj[(b0+s)*45 + j];
    }
    __syncthreads();

    // L3 dual: 145 -> 100 (p) / 100 (v), relu (K odd: 144 + remainder)
    if (tid < 200) {
        int half = tid >= 100;
        int n = half ? tid - 100 : tid;
        const float* W = g_wT + (half ? 77500 : 63000) + n;
        float bb = (half ? vb1 : pb1)[n];
        float a0=0.f, a1=0.f, c0=0.f, c1=0.f;
#pragma unroll 4
        for (int k = 0; k < 144; k += 2) {
            float w0 = W[k*100], w1 = W[(k+1)*100];
            a0 = fmaf(sA[0][k],   w0, a0);
            a1 = fmaf(sA[1][k],   w0, a1);
            c0 = fmaf(sA[0][k+1], w1, c0);
            c1 = fmaf(sA[1][k+1], w1, c1);
        }
        {   // k = 144
            float w0 = W[144*100];
            a0 = fmaf(sA[0][144], w0, a0);
            a1 = fmaf(sA[1][144], w0, a1);
        }
        sB[0][tid] = fmaxf(a0+c0+bb, 0.f);
        sB[1][tid] = fmaxf(a1+c1+bb, 0.f);
    }
    __syncthreads();

    // L4 dual: 100 -> 100 each head, relu (K even)
    float l4a = 0.f, l4b = 0.f;
    if (tid < 200) {
        int half = tid >= 100;
        int n = half ? tid - 100 : tid;
        int xoff = half ? 100 : 0;
        const float* W = g_wT + (half ? 102000 : 92000) + n;
        float bb = (half ? vb2 : pb2)[n];
        float a0=0.f, a1=0.f, c0=0.f, c1=0.f;
#pragma unroll 4
        for (int k = 0; k < 100; k += 2) {
            float w0 = W[k*100], w1 = W[(k+1)*100];
            a0 = fmaf(sB[0][xoff+k],   w0, a0);
            a1 = fmaf(sB[1][xoff+k],   w0, a1);
            c0 = fmaf(sB[0][xoff+k+1], w1, c0);
            c1 = fmaf(sB[1][xoff+k+1], w1, c1);
        }
        l4a = fmaxf(a0+c0+bb, 0.f);
        l4b = fmaxf(a1+c1+bb, 0.f);
    }
    __syncthreads();
    if (tid < 200) { sA[0][tid] = l4a; sA[1][tid] = l4b; }
    __syncthreads();

    // L5 dual: 100 -> 20 (p_r), 100 -> 40 (v), linear, to global
    if (tid < 20) {
        const float* W = g_wT + 112000 + tid;
        float bb = pb3[tid];
        float a0=0.f, a1=0.f, c0=0.f, c1=0.f;
#pragma unroll 4
        for (int k = 0; k < 100; k += 2) {
            float w0 = W[k*20], w1 = W[(k+1)*20];
            a0 = fmaf(sA[0][k],   w0, a0);
            a1 = fmaf(sA[1][k],   w0, a1);
            c0 = fmaf(sA[0][k+1], w1, c0);
            c1 = fmaf(sA[1][k+1], w1, c1);
        }
        g_pr[(b0+0)*20 + tid] = a0+c0+bb;
        g_pr[(b0+1)*20 + tid] = a1+c1+bb;
    } else if (tid >= 32 && tid < 72) {
        int n = tid - 32;
        const float* W = g_wT + 114000 + n;
        float bb = vb3[n];
        float a0=0.f, a1=0.f, c0=0.f, c1=0.f;
#pragma unroll 4
        for (int k = 0; k < 100; k += 2) {
            float w0 = W[k*40], w1 = W[(k+1)*40];
            a0 = fmaf(sA[0][100+k],   w0, a0);
            a1 = fmaf(sA[1][100+k],   w0, a1);
            c0 = fmaf(sA[0][100+k+1], w1, c0);
            c1 = fmaf(sA[1][100+k+1], w1, c1);
        }
        g_v[(b0+0)*40 + n] = a0+c0+bb;
        g_v[(b0+1)*40 + n] = a1+c1+bb;
    }
}

// ---------------- PDHG solver (scalar, proven; issue-bound at ~73%) + fused tail ------
struct Co {
    float a24,a25,a26,a27,a28,a29,a2a,a2b;
    float v0,v1,v2,v3,v4,v5;
    float fc0,fc1,fc2,fc3,fc4,fc5;
    float fe0,fe1,fe2,fe3,fe4,fe5,fe6,fe7;
};

__device__ __forceinline__ void amul(const Co& c, const float* s, float* az)
{
    az[0]  = s[4]+s[5]+s[6]+s[7]+s[8]+s[9];
    az[1]  = s[10]+s[11];
    {
        float p = c.a26*s[6] + c.a24*s[4] + c.a27*s[7] + c.a25*s[5];
        float q = c.a2a*s[10] + c.a28*s[8] + c.a2b*s[11] + c.a29*s[9];
        az[2] = p + q;
    }
    az[3]  = s[0] - c.v0*s[12] - c.v2*s[14];
    az[4]  = s[2] - c.v1*s[12] - c.v3*s[14];
    az[5]  = s[12] + s[14];
    az[6]  = s[1] - c.v2*s[13] - c.v4*s[15];
    az[7]  = s[3] - c.v3*s[13] - c.v5*s[15];
    az[8]  = s[13] + s[15];
    az[9]  = c.fc0*s[16] + c.fc2*s[18] - s[4];
    az[10] = c.fc1*s[16] + c.fc3*s[18] - s[6];
    az[11] = c.fc2*s[17] + c.fc4*s[19] - s[5];
    az[12] = c.fc3*s[17] + c.fc5*s[19] - s[7];
    az[13] = c.fe0*s[20] + c.fe2*s[21] - s[8];
    az[14] = c.fe1*s[20] + c.fe3*s[21] - s[10];
    az[15] = c.fe4*s[22] + c.fe6*s[23] - s[9];
    az[16] = c.fe5*s[22] + c.fe7*s[23] - s[11];
}

__device__ __forceinline__ void atmul(const Co& c, const float* y, float* g)
{
    g[0]  = y[3];  g[1] = y[6];  g[2] = y[4];  g[3] = y[7];
    g[4]  = y[0] + c.a24*y[2] - y[9];
    g[5]  = y[0] + c.a25*y[2] - y[11];
    g[6]  = y[0] + c.a26*y[2] - y[10];
    g[7]  = y[0] + c.a27*y[2] - y[12];
    g[8]  = y[0] + c.a28*y[2] - y[13];
    g[9]  = y[0] + c.a29*y[2] - y[15];
    g[10] = y[1] + c.a2a*y[2] - y[14];
    g[11] = y[1] + c.a2b*y[2] - y[16];
    g[12] = -c.v0*y[3] - c.v1*y[4] + y[5];
    g[13] = -c.v2*y[6] - c.v3*y[7] + y[8];
    g[14] = -c.v2*y[3] - c.v3*y[4] + y[5];
    g[15] = -c.v4*y[6] - c.v5*y[7] + y[8];
    g[16] = c.fc0*y[9]  + c.fc1*y[10];
    g[17] = c.fc2*y[11] + c.fc3*y[12];
    g[18] = c.fc2*y[9]  + c.fc3*y[10];
    g[19] = c.fc4*y[11] + c.fc5*y[12];
    g[20] = c.fe0*y[13] + c.fe1*y[14];
    g[21] = c.fe2*y[13] + c.fe3*y[14];
    g[22] = c.fe4*y[15] + c.fe5*y[16];
    g[23] = c.fe6*y[15] + c.fe7*y[16];
}

__global__ __launch_bounds__(32) void pdhg_kernel(const float* __restrict__ xtraj,
                                                  const float* __restrict__ x,
                                                  float* __restrict__ out)
{
    int p = blockIdx.x*blockDim.x + threadIdx.x;
    if (p >= NPROB) return;
    int b = p / TT, t = p % TT;
    const float* xt = xtraj + b*45;
    const float* xx = x + b*160;

    float r0 = xt[t], r1 = xt[5+t];
    float ddr0 = xt[30+t], ddr1 = xt[35+t], ddr2 = xt[40+t];

    Co c;
    c.fc0 = xx[20+t]; c.fc1 = xx[25+t]; c.fc2 = xx[30+t];
    c.fc3 = xx[35+t]; c.fc4 = xx[40+t]; c.fc5 = xx[45+t];
    float pe0 = xx[60+t], pe1 = xx[65+t], pe2 = xx[70+t], pe3 = xx[75+t];
    c.fe0 = xx[80+t];  c.fe1 = xx[85+t];  c.fe2 = xx[90+t];  c.fe3 = xx[95+t];
    c.fe4 = xx[100+t]; c.fe5 = xx[105+t]; c.fe6 = xx[110+t]; c.fe7 = xx[115+t];
    const float* vv = g_v + b*40;
    c.v0 = vv[t];    c.v1 = vv[5+t];  c.v2 = vv[10+t];
    c.v3 = vv[15+t]; c.v4 = vv[20+t]; c.v5 = vv[25+t];
    const float* pp = g_pr + b*20;
    float pr0 = pp[t], pr1 = pp[5+t], pr2 = pp[10+t], pr3 = pp[15+t];
    c.a24 = -(pr2 - r1); c.a25 = -(pr3 - r1); c.a26 = pr0 - r0; c.a27 = pr1 - r0;
    c.a28 = -(pe2 - r1); c.a29 = -(pe3 - r1); c.a2a = pe0 - r0; c.a2b = pe1 - r0;

    // ----- spectral norm: 25 power iterations -----
    float u[24];
#pragma unroll
    for (int i = 0; i < 24; i++) u[i] = 1.0f;
    for (int it = 0; it < 25; it++) {
        float w[17], un[24];
        amul(c, u, w);
        atmul(c, w, un);
        float s = 0.0f;
#pragma unroll
        for (int i = 0; i < 24; i++) s += un[i]*un[i];
        float inv = 1.0f/(sqrtf(s) + 1e-12f);
#pragma unroll
        for (int i = 0; i < 24; i++) u[i] = un[i]*inv;
    }
    float w17[17];
    amul(c, u, w17);
    float s = 0.0f;
#pragma unroll
    for (int e = 0; e < 17; e++) s += w17[e]*w17[e];
    float L = sqrtf(s);
    float tau = 0.9f/(L + 1e-8f);
    float sig = tau;

    // ----- PDHG, 400 iterations -----
    float z[24], zb[24], y[17];
#pragma unroll
    for (int i = 0; i < 24; i++) { z[i] = 0.0f; zb[i] = 0.0f; }
#pragma unroll
    for (int e = 0; e < 17; e++) y[e] = 0.0f;

    for (int it = 0; it < 400; it++) {
        float az[17];
        amul(c, zb, az);
        y[0] += sig*(az[0] - ddr0);
        y[1] += sig*(az[1] - ddr1);
        y[2] += sig*(az[2] - ddr2);
        y[3] += sig*az[3];
        y[4] += sig*az[4];
        y[5] += sig*(az[5] - 1.0f);
        y[6] += sig*az[6];
        y[7] += sig*az[7];
        y[8] += sig*(az[8] - 1.0f);
#pragma unroll
        for (int e = 9; e < 17; e++) y[e] += sig*az[e];

        float g[24];
        atmul(c, y, g);
#pragma unroll
        for (int i = 0; i < 24; i++) g[i] = z[i] - tau*g[i];

        float zn[24];
#pragma unroll
        for (int i = 0; i < 4; i++) zn[i] = g[i];
#pragma unroll
        for (int i = 4; i < 8; i++) {
            float a = fabsf(g[i]) - tau;
            zn[i] = (a > 0.0f) ? copysignf(a, g[i]) : 0.0f;
        }
#pragma unroll
        for (int i = 8; i < 12; i++) zn[i] = g[i];
#pragma unroll
        for (int i = 12; i < 24; i++) zn[i] = fmaxf(g[i], 0.0f);
#pragma unroll
        for (int i = 0; i < 24; i++) {
            zb[i] = 2.0f*zn[i] - z[i];
            z[i] = zn[i];
        }
    }

    // ----- write p, f parts (scaled by 100) -----
#pragma unroll
    for (int i = 0; i < 4; i++) out[b*100 + i*5 + t]      = 100.0f * z[i];
#pragma unroll
    for (int i = 0; i < 4; i++) out[b*100 + 20 + i*5 + t] = 100.0f * z[4+i];

    // ----- fused tail: this thread writes 12 of the 60 tail outputs of sample b -----
#pragma unroll
    for (int j = 0; j < 12; j++) {
        int jj = t*12 + j;
        if (jj < 20) out[b*100 + 40 + jj] = 1000.0f*(g_pr[b*20 + jj] - xx[jj]);
        else {
            int k = jj - 20;
            out[b*100 + 60 + k] = 1000.0f*(g_v[b*40 + k] - xx[120 + k]);
        }
    }
}

// ---------------- launch ----------------
extern "C" void kernel_launch(void* const* d_in, const int* in_sizes, int n_in,
                              void* d_out, int out_size)
{
    const float* xtraj = (const float*)d_in[0];
    const float* x     = (const float*)d_in[1];
    const float* x_img = (const float*)d_in[2];
    const float* cw1   = (const float*)d_in[3];
    const float* cb1   = (const float*)d_in[4];
    const float* cw2   = (const float*)d_in[5];
    const float* cb2   = (const float*)d_in[6];
    const float* w3    = (const float*)d_in[7];
    const float* b3    = (const float*)d_in[8];
    const float* w4    = (const float*)d_in[9];
    const float* b4    = (const float*)d_in[10];
    const float* pw1   = (const float*)d_in[11];
    const float* pb1   = (const float*)d_in[12];
    const float* pw2   = (const float*)d_in[13];
    const float* pb2   = (const float*)d_in[14];
    const float* pw3   = (const float*)d_in[15];
    const float* pb3   = (const float*)d_in[16];
    const float* vw1   = (const float*)d_in[17];
    const float* vb1   = (const float*)d_in[18];
    const float* vw2   = (const float*)d_in[19];
    const float* vb2   = (const float*)d_in[20];
    const float* vw3   = (const float*)d_in[21];
    const float* vb3   = (const float*)d_in[22];
    float* out = (float*)d_out;

    transpose_w<<<(118000 + 255)/256, 256>>>(w3, w4, pw1, vw1, pw2, vw2, pw3, vw3);
    conv1_kernel<<<BATCH, 400>>>(x_img, cw1, cb1);
    conv2_kernel<<<BATCH, 320>>>(cw2, cb2);
    mlp_kernel<<<BATCH/2, 256>>>(xtraj, b3, b4, pb1, vb1, pb2, vb2, pb3, vb3);
    pdhg_kernel<<<(NPROB + 31)/32, 32>>>(xtraj, x, out);
}